// round 3
// baseline (speedup 1.0000x reference)
#include <cuda_runtime.h>
#include <cstdint>

// VQ via mma.sync tf32 (3xTF32 exact-fp32 emulation), baseline PTX (no tcgen05).
// score[m][k] = x_m . e_k (hh + lh + hl), best = argmax(score - 0.5||e||^2)

#define D    64
#define K    512
#define MT   128     // pixels per CTA
#define T    256     // threads per CTA (8 warps, 16 pixels/warp)
#define NB   128     // codes per N-block
#define NBLK 4

// SMEM layout (bytes)
#define SX_OFF    0                      // x tile fp32 [d][m] = [64][128]   32KB
#define B_OFF     32768                  // 2 bufs x (hi 32KB + lo 32KB)    128KB
#define BUF_SZ    65536
#define SHES_OFF  (B_OFF + 2 * BUF_SZ)   // 512 f32
#define SBEST_OFF (SHES_OFF + 2048)      // 128 int
#define SMEM_SZ   (SBEST_OFF + 512)

__device__ float g_ehi[K * D];   // tf32-hi codebook, k%4-interleaved rows
__device__ float g_elo[K * D];   // tf32-lo codebook, same layout
__device__ float g_hes[K];       // 0.5*||e||^2

// ---------------- helpers ----------------
__device__ __forceinline__ uint32_t smem_u32(const void* p) {
    uint32_t a;
    asm("{ .reg .u64 t; cvta.to.shared.u64 t, %1; cvt.u32.u64 %0, t; }" : "=r"(a) : "l"(p));
    return a;
}
__device__ __forceinline__ uint32_t tf32_bits(float v) {
    uint32_t u; asm("cvt.rna.tf32.f32 %0, %1;" : "=r"(u) : "f"(v));
    return u;
}
#define MMA_TF32(c, a0, a1, a2, a3, b0, b1)                                      \
    asm volatile("mma.sync.aligned.m16n8k8.row.col.f32.tf32.tf32.f32 "           \
        "{%0,%1,%2,%3},{%4,%5,%6,%7},{%8,%9},{%0,%1,%2,%3};"                     \
        : "+f"((c)[0]), "+f"((c)[1]), "+f"((c)[2]), "+f"((c)[3])                  \
        : "r"(a0), "r"(a1), "r"(a2), "r"(a3), "r"(b0), "r"(b1))

__device__ __forceinline__ void cp16(uint32_t dst, const void* src) {
    asm volatile("cp.async.cg.shared.global [%0], [%1], 16;" :: "r"(dst), "l"(src) : "memory");
}
#define CP_COMMIT() asm volatile("cp.async.commit_group;" ::: "memory")
#define CP_WAIT(n)  asm volatile("cp.async.wait_group %0;" :: "n"(n) : "memory")

// ---------------- prep: split codebook, permuted rows, half norms ----------------
// row layout: element d stored at (d%4)*16 + d/4  -> frag loads become LDS.128
__global__ void vq_prep(const float* __restrict__ embed) {
    int k = blockIdx.x, d = threadIdx.x;
    float v = embed[k * D + d];
    uint32_t hb = tf32_bits(v);
    float h = __uint_as_float(hb);
    int p = (d & 3) * 16 + (d >> 2);
    g_ehi[k * D + p] = h;
    g_elo[k * D + p] = __uint_as_float(tf32_bits(v - h));
    float s = v * v;
    #pragma unroll
    for (int o = 16; o > 0; o >>= 1) s += __shfl_down_sync(0xffffffffu, s, o);
    __shared__ float ws[2];
    if ((d & 31) == 0) ws[d >> 5] = s;
    __syncthreads();
    if (d == 0) g_hes[k] = 0.5f * (ws[0] + ws[1]);
}

// ---------------- main ----------------
__device__ __forceinline__ void cp_block(uint32_t sb, int blk, int buf, int tid) {
    uint32_t dst = sb + B_OFF + buf * BUF_SZ;
    const float* sh = g_ehi + blk * NB * D;
    const float* sl = g_elo + blk * NB * D;
    #pragma unroll
    for (int t = 0; t < 8; t++) {
        int c = tid + t * T;                 // 16B chunk id, 2048 per half
        cp16(dst + c * 16, sh + c * 4);
        cp16(dst + 32768 + c * 16, sl + c * 4);
    }
}

__global__ void __launch_bounds__(T, 1) vq_main(const float* __restrict__ x,
                                                const float* __restrict__ embed,
                                                float* __restrict__ outq,
                                                float* __restrict__ outi) {
    extern __shared__ __align__(1024) char smem[];
    uint32_t sb = smem_u32(smem);
    const int tid = threadIdx.x, wid = tid >> 5, lane = tid & 31;
    const int q = lane >> 2, r = lane & 3;
    const int n0 = blockIdx.x * MT;
    const int b = n0 >> 12, hw0 = n0 & 4095;

    float* sx = (float*)(smem + SX_OFF);         // [d][128]
    float* shes = (float*)(smem + SHES_OFF);
    int* sbest = (int*)(smem + SBEST_OFF);

    // prefetch first two codebook blocks
    cp_block(sb, 0, 0, tid); CP_COMMIT();
    cp_block(sb, 1, 1, tid); CP_COMMIT();

    // stage x tile: sx[c][j] = x[b][c][hw0+j]  (coalesced float4, conflict-free)
    #pragma unroll
    for (int t = 0; t < 8; t++) {
        int i = tid + t * T;                     // 2048 float4-groups/4 -> 64*32
        int c = i >> 5, j4 = (i & 31) << 2;
        float4 v = *(const float4*)(x + (((size_t)(b * D + c)) << 12) + hw0 + j4);
        *(float4*)(sx + c * MT + j4) = v;
    }
    for (int i = tid; i < K; i += T) shes[i] = g_hes[i];
    __syncthreads();

    // per-warp A fragments in registers: rows m0+q, m0+q+8; Areg[t] = A[m][k=r+4t]
    const int m0 = wid * 16;
    uint32_t Ah0[16], Al0[16], Ah1[16], Al1[16];
    #pragma unroll
    for (int t = 0; t < 16; t++) {
        int k = r + 4 * t;
        float v0 = sx[k * MT + m0 + q];
        float v1 = sx[k * MT + m0 + q + 8];
        Ah0[t] = tf32_bits(v0); Al0[t] = tf32_bits(v0 - __uint_as_float(Ah0[t]));
        Ah1[t] = tf32_bits(v1); Al1[t] = tf32_bits(v1 - __uint_as_float(Ah1[t]));
    }

    float best_s0 = -3.0e38f, best_s1 = -3.0e38f;
    int best_i0 = 0, best_i1 = 0;

    for (int blk = 0; blk < NBLK; blk++) {
        if (blk < NBLK - 1) { CP_WAIT(1); } else { CP_WAIT(0); }
        __syncthreads();
        const char* bufb = smem + B_OFF + (blk & 1) * BUF_SZ;

        #pragma unroll 1
        for (int ntp = 0; ntp < 8; ntp++) {
            uint32_t Bh[2][16], Bl[2][16];
            #pragma unroll
            for (int tile = 0; tile < 2; tile++) {
                int n = (ntp * 2 + tile) * 8 + q;
                const uint4* ph = (const uint4*)(bufb + n * 256 + r * 64);
                const uint4* pl = (const uint4*)(bufb + 32768 + n * 256 + r * 64);
                #pragma unroll
                for (int u = 0; u < 4; u++) {
                    uint4 vh = ph[u], vl = pl[u];
                    Bh[tile][4*u] = vh.x; Bh[tile][4*u+1] = vh.y;
                    Bh[tile][4*u+2] = vh.z; Bh[tile][4*u+3] = vh.w;
                    Bl[tile][4*u] = vl.x; Bl[tile][4*u+1] = vl.y;
                    Bl[tile][4*u+2] = vl.z; Bl[tile][4*u+3] = vl.w;
                }
            }
            float acc[6][4];
            #pragma unroll
            for (int i = 0; i < 6; i++)
                #pragma unroll
                for (int c = 0; c < 4; c++) acc[i][c] = 0.0f;

            #pragma unroll
            for (int ks = 0; ks < 8; ks++) {
                int t0 = 2 * ks, t1 = 2 * ks + 1;
                #pragma unroll
                for (int tile = 0; tile < 2; tile++) {
                    MMA_TF32(acc[tile*3+0], Ah0[t0], Ah1[t0], Ah0[t1], Ah1[t1],
                             Bh[tile][t0], Bh[tile][t1]);
                    MMA_TF32(acc[tile*3+1], Al0[t0], Al1[t0], Al0[t1], Al1[t1],
                             Bh[tile][t0], Bh[tile][t1]);
                    MMA_TF32(acc[tile*3+2], Ah0[t0], Ah1[t0], Ah0[t1], Ah1[t1],
                             Bl[tile][t0], Bl[tile][t1]);
                }
            }
            #pragma unroll
            for (int tile = 0; tile < 2; tile++) {
                int cb = blk * NB + (ntp * 2 + tile) * 8 + 2 * r;
                float h0 = shes[cb], h1 = shes[cb + 1];
                float s00 = acc[tile*3][0] + acc[tile*3+1][0] + acc[tile*3+2][0] - h0;
                float s01 = acc[tile*3][1] + acc[tile*3+1][1] + acc[tile*3+2][1] - h1;
                float s10 = acc[tile*3][2] + acc[tile*3+1][2] + acc[tile*3+2][2] - h0;
                float s11 = acc[tile*3][3] + acc[tile*3+1][3] + acc[tile*3+2][3] - h1;
                if (s00 > best_s0) { best_s0 = s00; best_i0 = cb; }
                if (s01 > best_s0) { best_s0 = s01; best_i0 = cb + 1; }
                if (s10 > best_s1) { best_s1 = s10; best_i1 = cb; }
                if (s11 > best_s1) { best_s1 = s11; best_i1 = cb + 1; }
            }
        }
        if (blk + 2 < NBLK) {
            __syncthreads();                       // all warps done reading this buf
            cp_block(sb, blk + 2, blk & 1, tid);
            CP_COMMIT();
        }
    }

    // reduce across the 4 lanes sharing each pixel row (ties -> smallest index)
    #pragma unroll
    for (int off = 1; off <= 2; off <<= 1) {
        float so0 = __shfl_xor_sync(0xffffffffu, best_s0, off);
        int   io0 = __shfl_xor_sync(0xffffffffu, best_i0, off);
        float so1 = __shfl_xor_sync(0xffffffffu, best_s1, off);
        int   io1 = __shfl_xor_sync(0xffffffffu, best_i1, off);
        if (so0 > best_s0 || (so0 == best_s0 && io0 < best_i0)) { best_s0 = so0; best_i0 = io0; }
        if (so1 > best_s1 || (so1 == best_s1 && io1 < best_i1)) { best_s1 = so1; best_i1 = io1; }
    }
    if (r == 0) {
        sbest[m0 + q] = best_i0;
        sbest[m0 + q + 8] = best_i1;
    }
    __syncthreads();

    // outputs: gathered codebook rows (NHWC) + indices (float)
    #pragma unroll
    for (int t = 0; t < 8; t++) {
        int i = tid + t * T;                      // MT*16 = 2048 float4 writes
        int j = i >> 4, c4 = i & 15;
        int idx = sbest[j];
        float4 v = *(const float4*)(embed + idx * D + (c4 << 2));
        *(float4*)(outq + ((size_t)(n0 + j)) * D + (c4 << 2)) = v;
    }
    if (outi)
        for (int i = tid; i < MT; i += T) outi[n0 + i] = (float)sbest[i];
}

// ---------------------------------------------------------------------------
extern "C" void kernel_launch(void* const* d_in, const int* in_sizes, int n_in,
                              void* d_out, int out_size) {
    const float* x = (const float*)d_in[0];
    const float* embed = (const float*)d_in[1];
    float* out = (float*)d_out;

    const int N = in_sizes[0] / D;
    float* outi = nullptr;
    if (out_size >= N * D + N) outi = out + (size_t)N * D;

    cudaFuncSetAttribute(vq_main, cudaFuncAttributeMaxDynamicSharedMemorySize, SMEM_SZ);
    vq_prep<<<K, D>>>(embed);
    vq_main<<<N / MT, T, SMEM_SZ>>>(x, embed, out, outi);
}

// round 4
// speedup vs baseline: 1.3878x; 1.3878x over previous
#include <cuda_runtime.h>
#include <cstdint>

// VQ via mma.sync tf32 (3xTF32 exact-fp32 emulation), baseline PTX (no tcgen05).
// score[m][k] = x_m . e_k (hh + lh + hl), best = argmax(score - 0.5||e||^2)
// R4: conflict-free 16B-slot swizzle for B smem (was 4-way conflicted).

#define D    64
#define K    512
#define MT   128     // pixels per CTA
#define T    256     // threads per CTA (8 warps, 16 pixels/warp)
#define NB   128     // codes per N-block
#define NBLK 4

// SMEM layout (bytes)
#define SX_OFF    0                      // x tile fp32 [d][m] = [64][128]   32KB
#define B_OFF     32768                  // 2 bufs x (hi 32KB + lo 32KB)    128KB
#define BUF_SZ    65536
#define SHES_OFF  (B_OFF + 2 * BUF_SZ)   // 512 f32
#define SBEST_OFF (SHES_OFF + 2048)      // 128 int
#define SMEM_SZ   (SBEST_OFF + 512)

__device__ float g_ehi[K * D];   // tf32-hi codebook, k%4-interleaved rows
__device__ float g_elo[K * D];   // tf32-lo codebook, same layout
__device__ float g_hes[K];       // 0.5*||e||^2

// ---------------- helpers ----------------
__device__ __forceinline__ uint32_t smem_u32(const void* p) {
    uint32_t a;
    asm("{ .reg .u64 t; cvta.to.shared.u64 t, %1; cvt.u32.u64 %0, t; }" : "=r"(a) : "l"(p));
    return a;
}
__device__ __forceinline__ uint32_t tf32_bits(float v) {
    uint32_t u; asm("cvt.rna.tf32.f32 %0, %1;" : "=r"(u) : "f"(v));
    return u;
}
#define MMA_TF32(c, a0, a1, a2, a3, b0, b1)                                      \
    asm volatile("mma.sync.aligned.m16n8k8.row.col.f32.tf32.tf32.f32 "           \
        "{%0,%1,%2,%3},{%4,%5,%6,%7},{%8,%9},{%0,%1,%2,%3};"                     \
        : "+f"((c)[0]), "+f"((c)[1]), "+f"((c)[2]), "+f"((c)[3])                  \
        : "r"(a0), "r"(a1), "r"(a2), "r"(a3), "r"(b0), "r"(b1))

__device__ __forceinline__ void cp16(uint32_t dst, const void* src) {
    asm volatile("cp.async.cg.shared.global [%0], [%1], 16;" :: "r"(dst), "l"(src) : "memory");
}
#define CP_COMMIT() asm volatile("cp.async.commit_group;" ::: "memory")
#define CP_WAIT(n)  asm volatile("cp.async.wait_group %0;" :: "n"(n) : "memory")

// ---------------- prep: split codebook, permuted rows, half norms ----------------
// row layout: element d stored at (d%4)*16 + d/4  -> frag loads become LDS.128
__global__ void vq_prep(const float* __restrict__ embed) {
    int k = blockIdx.x, d = threadIdx.x;
    float v = embed[k * D + d];
    uint32_t hb = tf32_bits(v);
    float h = __uint_as_float(hb);
    int p = (d & 3) * 16 + (d >> 2);
    g_ehi[k * D + p] = h;
    g_elo[k * D + p] = __uint_as_float(tf32_bits(v - h));
    float s = v * v;
    #pragma unroll
    for (int o = 16; o > 0; o >>= 1) s += __shfl_down_sync(0xffffffffu, s, o);
    __shared__ float ws[2];
    if ((d & 31) == 0) ws[d >> 5] = s;
    __syncthreads();
    if (d == 0) g_hes[k] = 0.5f * (ws[0] + ws[1]);
}

// ---------------- main ----------------
// B smem swizzle: logical 16B chunk (r,u) of row n lives at slot (4u + r + 4n)&15.
// Source (g_ehi interleaved row) holds chunk (r,u) at byte offset r*64 + u*16,
// i.e. logical slot L = 4r + u  ->  dst slot = (4*(L&3) + (L>>2) + 4n) & 15.
__device__ __forceinline__ void cp_block(uint32_t sb, int blk, int buf, int tid) {
    uint32_t dst = sb + B_OFF + buf * BUF_SZ;
    const float* sh = g_ehi + blk * NB * D;
    const float* sl = g_elo + blk * NB * D;
    #pragma unroll
    for (int t = 0; t < 8; t++) {
        int c = tid + t * T;                 // 16B chunk id, 2048 per half
        int n = c >> 4, L = c & 15;
        int s = (((L & 3) << 2) + (L >> 2) + (n << 2)) & 15;
        uint32_t d0 = dst + n * 256 + s * 16;
        cp16(d0, sh + c * 4);
        cp16(d0 + 32768, sl + c * 4);
    }
}

__global__ void __launch_bounds__(T, 1) vq_main(const float* __restrict__ x,
                                                const float* __restrict__ embed,
                                                float* __restrict__ outq,
                                                float* __restrict__ outi) {
    extern __shared__ __align__(1024) char smem[];
    uint32_t sb = smem_u32(smem);
    const int tid = threadIdx.x, wid = tid >> 5, lane = tid & 31;
    const int q = lane >> 2, r = lane & 3;
    const int n0 = blockIdx.x * MT;
    const int b = n0 >> 12, hw0 = n0 & 4095;

    float* sx = (float*)(smem + SX_OFF);         // [d][128]
    float* shes = (float*)(smem + SHES_OFF);
    int* sbest = (int*)(smem + SBEST_OFF);

    // prefetch first two codebook blocks
    cp_block(sb, 0, 0, tid); CP_COMMIT();
    cp_block(sb, 1, 1, tid); CP_COMMIT();

    // stage x tile: sx[c][j] = x[b][c][hw0+j]  (coalesced float4, conflict-free)
    #pragma unroll
    for (int t = 0; t < 8; t++) {
        int i = tid + t * T;                     // 2048 float4-groups -> 64*32
        int c = i >> 5, j4 = (i & 31) << 2;
        float4 v = *(const float4*)(x + (((size_t)(b * D + c)) << 12) + hw0 + j4);
        *(float4*)(sx + c * MT + j4) = v;
    }
    for (int i = tid; i < K; i += T) shes[i] = g_hes[i];
    __syncthreads();

    // per-warp A fragments in registers: rows m0+q, m0+q+8; Areg[t] = A[m][k=r+4t]
    const int m0 = wid * 16;
    uint32_t Ah0[16], Al0[16], Ah1[16], Al1[16];
    #pragma unroll
    for (int t = 0; t < 16; t++) {
        int k = r + 4 * t;
        float v0 = sx[k * MT + m0 + q];
        float v1 = sx[k * MT + m0 + q + 8];
        Ah0[t] = tf32_bits(v0); Al0[t] = tf32_bits(v0 - __uint_as_float(Ah0[t]));
        Ah1[t] = tf32_bits(v1); Al1[t] = tf32_bits(v1 - __uint_as_float(Ah1[t]));
    }

    float best_s0 = -3.0e38f, best_s1 = -3.0e38f;
    int best_i0 = 0, best_i1 = 0;

    for (int blk = 0; blk < NBLK; blk++) {
        if (blk < NBLK - 1) { CP_WAIT(1); } else { CP_WAIT(0); }
        __syncthreads();
        const char* bufb = smem + B_OFF + (blk & 1) * BUF_SZ;

        #pragma unroll 1
        for (int ntp = 0; ntp < 8; ntp++) {
            uint32_t Bh[2][16], Bl[2][16];
            #pragma unroll
            for (int tile = 0; tile < 2; tile++) {
                int n = (ntp * 2 + tile) * 8 + q;
                const char* rowb = bufb + n * 256;
                int s0 = (r + (n << 2)) & 15;     // slot = (4u + r + 4n) & 15
                #pragma unroll
                for (int u = 0; u < 4; u++) {
                    int s = (s0 + (u << 2)) & 15;
                    uint4 vh = *(const uint4*)(rowb + s * 16);
                    uint4 vl = *(const uint4*)(rowb + 32768 + s * 16);
                    Bh[tile][4*u] = vh.x; Bh[tile][4*u+1] = vh.y;
                    Bh[tile][4*u+2] = vh.z; Bh[tile][4*u+3] = vh.w;
                    Bl[tile][4*u] = vl.x; Bl[tile][4*u+1] = vl.y;
                    Bl[tile][4*u+2] = vl.z; Bl[tile][4*u+3] = vl.w;
                }
            }
            float acc[6][4];
            #pragma unroll
            for (int i = 0; i < 6; i++)
                #pragma unroll
                for (int c = 0; c < 4; c++) acc[i][c] = 0.0f;

            #pragma unroll
            for (int ks = 0; ks < 8; ks++) {
                int t0 = 2 * ks, t1 = 2 * ks + 1;
                #pragma unroll
                for (int tile = 0; tile < 2; tile++) {
                    MMA_TF32(acc[tile*3+0], Ah0[t0], Ah1[t0], Ah0[t1], Ah1[t1],
                             Bh[tile][t0], Bh[tile][t1]);
                    MMA_TF32(acc[tile*3+1], Al0[t0], Al1[t0], Al0[t1], Al1[t1],
                             Bh[tile][t0], Bh[tile][t1]);
                    MMA_TF32(acc[tile*3+2], Ah0[t0], Ah1[t0], Ah0[t1], Ah1[t1],
                             Bl[tile][t0], Bl[tile][t1]);
                }
            }
            #pragma unroll
            for (int tile = 0; tile < 2; tile++) {
                int cb = blk * NB + (ntp * 2 + tile) * 8 + 2 * r;
                float h0 = shes[cb], h1 = shes[cb + 1];
                float s00 = acc[tile*3][0] + acc[tile*3+1][0] + acc[tile*3+2][0] - h0;
                float s01 = acc[tile*3][1] + acc[tile*3+1][1] + acc[tile*3+2][1] - h1;
                float s10 = acc[tile*3][2] + acc[tile*3+1][2] + acc[tile*3+2][2] - h0;
                float s11 = acc[tile*3][3] + acc[tile*3+1][3] + acc[tile*3+2][3] - h1;
                if (s00 > best_s0) { best_s0 = s00; best_i0 = cb; }
                if (s01 > best_s0) { best_s0 = s01; best_i0 = cb + 1; }
                if (s10 > best_s1) { best_s1 = s10; best_i1 = cb; }
                if (s11 > best_s1) { best_s1 = s11; best_i1 = cb + 1; }
            }
        }
        if (blk + 2 < NBLK) {
            __syncthreads();                       // all warps done reading this buf
            cp_block(sb, blk + 2, blk & 1, tid);
            CP_COMMIT();
        }
    }

    // reduce across the 4 lanes sharing each pixel row (ties -> smallest index)
    #pragma unroll
    for (int off = 1; off <= 2; off <<= 1) {
        float so0 = __shfl_xor_sync(0xffffffffu, best_s0, off);
        int   io0 = __shfl_xor_sync(0xffffffffu, best_i0, off);
        float so1 = __shfl_xor_sync(0xffffffffu, best_s1, off);
        int   io1 = __shfl_xor_sync(0xffffffffu, best_i1, off);
        if (so0 > best_s0 || (so0 == best_s0 && io0 < best_i0)) { best_s0 = so0; best_i0 = io0; }
        if (so1 > best_s1 || (so1 == best_s1 && io1 < best_i1)) { best_s1 = so1; best_i1 = io1; }
    }
    if (r == 0) {
        sbest[m0 + q] = best_i0;
        sbest[m0 + q + 8] = best_i1;
    }
    __syncthreads();

    // outputs: gathered codebook rows (NHWC) + indices (float)
    #pragma unroll
    for (int t = 0; t < 8; t++) {
        int i = tid + t * T;                      // MT*16 = 2048 float4 writes
        int j = i >> 4, c4 = i & 15;
        int idx = sbest[j];
        float4 v = *(const float4*)(embed + idx * D + (c4 << 2));
        *(float4*)(outq + ((size_t)(n0 + j)) * D + (c4 << 2)) = v;
    }
    if (outi)
        for (int i = tid; i < MT; i += T) outi[n0 + i] = (float)sbest[i];
}

// ---------------------------------------------------------------------------
extern "C" void kernel_launch(void* const* d_in, const int* in_sizes, int n_in,
                              void* d_out, int out_size) {
    const float* x = (const float*)d_in[0];
    const float* embed = (const float*)d_in[1];
    float* out = (float*)d_out;

    const int N = in_sizes[0] / D;
    float* outi = nullptr;
    if (out_size >= N * D + N) outi = out + (size_t)N * D;

    cudaFuncSetAttribute(vq_main, cudaFuncAttributeMaxDynamicSharedMemorySize, SMEM_SZ);
    vq_prep<<<K, D>>>(embed);
    vq_main<<<N / MT, T, SMEM_SZ>>>(x, embed, out, outi);
}

// round 6
// speedup vs baseline: 1.3967x; 1.0065x over previous
#include <cuda_runtime.h>
#include <cstdint>

// VQ via mma.sync tf32 (3xTF32 exact-fp32 emulation), baseline PTX.
// R6: fix R5's A-fragment index (t0 = 4u+2kk, was 8u+2kk -> OOB garbage).
// 512 threads (16 warps), N-split across warp groups to feed tensor pipe.

#define D    64
#define K    512
#define MT   128     // pixels per CTA
#define T    512     // threads per CTA (16 warps)
#define NB   128     // codes per N-block
#define NBLK 4

// SMEM layout (bytes)
#define SX_OFF    0                      // x tile fp32 [d][m] = [64][128]   32KB
#define B_OFF     32768                  // 2 bufs x (hi 32KB + lo 32KB)    128KB
#define BUF_SZ    65536
#define SHES_OFF  (B_OFF + 2 * BUF_SZ)   // 512 f32
#define SBEST_OFF (SHES_OFF + 2048)      // 128 u64
#define SMEM_SZ   (SBEST_OFF + 1024)

__device__ float g_ehi[K * D];   // tf32-hi codebook, k%4-interleaved rows
__device__ float g_elo[K * D];   // tf32-lo codebook, same layout
__device__ float g_hes[K];       // 0.5*||e||^2

// ---------------- helpers ----------------
__device__ __forceinline__ uint32_t smem_u32(const void* p) {
    uint32_t a;
    asm("{ .reg .u64 t; cvta.to.shared.u64 t, %1; cvt.u32.u64 %0, t; }" : "=r"(a) : "l"(p));
    return a;
}
__device__ __forceinline__ uint32_t tf32_bits(float v) {
    uint32_t u; asm("cvt.rna.tf32.f32 %0, %1;" : "=r"(u) : "f"(v));
    return u;
}
#define MMA_TF32(c, a0, a1, a2, a3, b0, b1)                                      \
    asm volatile("mma.sync.aligned.m16n8k8.row.col.f32.tf32.tf32.f32 "           \
        "{%0,%1,%2,%3},{%4,%5,%6,%7},{%8,%9},{%0,%1,%2,%3};"                     \
        : "+f"((c)[0]), "+f"((c)[1]), "+f"((c)[2]), "+f"((c)[3])                  \
        : "r"(a0), "r"(a1), "r"(a2), "r"(a3), "r"(b0), "r"(b1))

__device__ __forceinline__ void cp16(uint32_t dst, const void* src) {
    asm volatile("cp.async.cg.shared.global [%0], [%1], 16;" :: "r"(dst), "l"(src) : "memory");
}
#define CP_COMMIT() asm volatile("cp.async.commit_group;" ::: "memory")
#define CP_WAIT(n)  asm volatile("cp.async.wait_group %0;" :: "n"(n) : "memory")

// ---------------- prep: split codebook, permuted rows, half norms ----------------
// row layout: element d stored at (d%4)*16 + d/4  -> frag loads become LDS.128
__global__ void vq_prep(const float* __restrict__ embed) {
    int k = blockIdx.x, d = threadIdx.x;
    float v = embed[k * D + d];
    uint32_t hb = tf32_bits(v);
    float h = __uint_as_float(hb);
    int p = (d & 3) * 16 + (d >> 2);
    g_ehi[k * D + p] = h;
    g_elo[k * D + p] = __uint_as_float(tf32_bits(v - h));
    float s = v * v;
    #pragma unroll
    for (int o = 16; o > 0; o >>= 1) s += __shfl_down_sync(0xffffffffu, s, o);
    __shared__ float ws[2];
    if ((d & 31) == 0) ws[d >> 5] = s;
    __syncthreads();
    if (d == 0) g_hes[k] = 0.5f * (ws[0] + ws[1]);
}

// ---------------- main ----------------
// B smem: 16B chunk (logical slot L = 4r+u) of row n stored at slot (4*(L&3)+(L>>2)+4n)&15
// so reader phases (fixed u; lanes q,r) hit all 8 bank-quads -> conflict-free.
__device__ __forceinline__ void cp_block(uint32_t sb, int blk, int buf, int tid) {
    uint32_t dst = sb + B_OFF + buf * BUF_SZ;
    const float* sh = g_ehi + blk * NB * D;
    const float* sl = g_elo + blk * NB * D;
    #pragma unroll
    for (int t = 0; t < 4; t++) {
        int c = tid + t * T;                 // 16B chunk id, 2048 per half
        int n = c >> 4, L = c & 15;
        int s = (((L & 3) << 2) + (L >> 2) + (n << 2)) & 15;
        uint32_t d0 = dst + n * 256 + s * 16;
        cp16(d0, sh + c * 4);
        cp16(d0 + 32768, sl + c * 4);
    }
}

__global__ void __launch_bounds__(T, 1) vq_main(const float* __restrict__ x,
                                                const float* __restrict__ embed,
                                                float* __restrict__ outq,
                                                float* __restrict__ outi) {
    extern __shared__ __align__(1024) char smem[];
    uint32_t sb = smem_u32(smem);
    const int tid = threadIdx.x, wid = tid >> 5, lane = tid & 31;
    const int q = lane >> 2, r = lane & 3;
    const int wm = wid & 7;                  // m-group (16 pixels)
    const int wg = wid >> 3;                 // n-half (0: codes [0,64), 1: [64,128))
    const int n0 = blockIdx.x * MT;
    const int b = n0 >> 12, hw0 = n0 & 4095;

    float* sx = (float*)(smem + SX_OFF);     // [d][128]
    float* shes = (float*)(smem + SHES_OFF);
    unsigned long long* sbest = (unsigned long long*)(smem + SBEST_OFF);

    // prefetch first two codebook blocks
    cp_block(sb, 0, 0, tid); CP_COMMIT();
    cp_block(sb, 1, 1, tid); CP_COMMIT();

    // stage x tile: sx[c][j] = x[b][c][hw0+j]  (coalesced float4, conflict-free)
    #pragma unroll
    for (int t = 0; t < 4; t++) {
        int i = tid + t * T;                 // 2048 float4-groups -> 64*32
        int c = i >> 5, j4 = (i & 31) << 2;
        float4 v = *(const float4*)(x + (((size_t)(b * D + c)) << 12) + hw0 + j4);
        *(float4*)(sx + c * MT + j4) = v;
    }
    if (tid < K) shes[tid] = g_hes[tid];
    if (tid < MT) sbest[tid] = 0ull;
    __syncthreads();

    // per-warp A fragments: rows m0+q, m0+q+8; frag t covers k = r + 4t
    const int m0 = wm * 16;
    uint32_t Ah0[16], Al0[16], Ah1[16], Al1[16];
    #pragma unroll
    for (int t = 0; t < 16; t++) {
        int k = r + 4 * t;
        float v0 = sx[k * MT + m0 + q];
        float v1 = sx[k * MT + m0 + q + 8];
        Ah0[t] = tf32_bits(v0); Al0[t] = tf32_bits(v0 - __uint_as_float(Ah0[t]));
        Ah1[t] = tf32_bits(v1); Al1[t] = tf32_bits(v1 - __uint_as_float(Ah1[t]));
    }

    float best_s0 = -3.0e38f, best_s1 = -3.0e38f;
    int best_i0 = 0, best_i1 = 0;

    for (int blk = 0; blk < NBLK; blk++) {
        if (blk < NBLK - 1) { CP_WAIT(1); } else { CP_WAIT(0); }
        __syncthreads();
        const char* bufb = smem + B_OFF + (blk & 1) * BUF_SZ;

        #pragma unroll 1
        for (int ntp = 0; ntp < 4; ntp++) {
            const int nt0 = wg * 8 + ntp * 2;        // first of 2 n-tiles
            float acc[6][4];
            #pragma unroll
            for (int i = 0; i < 6; i++)
                #pragma unroll
                for (int c = 0; c < 4; c++) acc[i][c] = 0.0f;

            // interleave B loads (per-u, 16 live regs) with MMAs
            #pragma unroll
            for (int u = 0; u < 4; u++) {
                uint32_t Bh[2][4], Bl[2][4];
                #pragma unroll
                for (int tile = 0; tile < 2; tile++) {
                    int n = (nt0 + tile) * 8 + q;
                    const char* rowb = bufb + n * 256;
                    int s = ((r + (n << 2)) + (u << 2)) & 15;
                    uint4 vh = *(const uint4*)(rowb + s * 16);
                    uint4 vl = *(const uint4*)(rowb + 32768 + s * 16);
                    Bh[tile][0] = vh.x; Bh[tile][1] = vh.y;
                    Bh[tile][2] = vh.z; Bh[tile][3] = vh.w;
                    Bl[tile][0] = vl.x; Bl[tile][1] = vl.y;
                    Bl[tile][2] = vl.z; Bl[tile][3] = vl.w;
                }
                #pragma unroll
                for (int kk = 0; kk < 2; kk++) {     // ks = 2u + kk
                    int t0 = 4 * u + 2 * kk;         // = 2*ks  (R5 bug: was 8u+2kk)
                    int t1 = t0 + 1;
                    #pragma unroll
                    for (int tile = 0; tile < 2; tile++) {
                        MMA_TF32(acc[tile*3+0], Ah0[t0], Ah1[t0], Ah0[t1], Ah1[t1],
                                 Bh[tile][2*kk], Bh[tile][2*kk+1]);
                        MMA_TF32(acc[tile*3+1], Al0[t0], Al1[t0], Al0[t1], Al1[t1],
                                 Bh[tile][2*kk], Bh[tile][2*kk+1]);
                        MMA_TF32(acc[tile*3+2], Ah0[t0], Ah1[t0], Ah0[t1], Ah1[t1],
                                 Bl[tile][2*kk], Bl[tile][2*kk+1]);
                    }
                }
            }
            #pragma unroll
            for (int tile = 0; tile < 2; tile++) {
                int cb = blk * NB + (nt0 + tile) * 8 + 2 * r;
                float h0 = shes[cb], h1 = shes[cb + 1];
                float s00 = acc[tile*3][0] + acc[tile*3+1][0] + acc[tile*3+2][0] - h0;
                float s01 = acc[tile*3][1] + acc[tile*3+1][1] + acc[tile*3+2][1] - h1;
                float s10 = acc[tile*3][2] + acc[tile*3+1][2] + acc[tile*3+2][2] - h0;
                float s11 = acc[tile*3][3] + acc[tile*3+1][3] + acc[tile*3+2][3] - h1;
                if (s00 > best_s0) { best_s0 = s00; best_i0 = cb; }
                if (s01 > best_s0) { best_s0 = s01; best_i0 = cb + 1; }
                if (s10 > best_s1) { best_s1 = s10; best_i1 = cb; }
                if (s11 > best_s1) { best_s1 = s11; best_i1 = cb + 1; }
            }
        }
        if (blk + 2 < NBLK) {
            __syncthreads();                       // all warps done reading this buf
            cp_block(sb, blk + 2, blk & 1, tid);
            CP_COMMIT();
        }
    }

    // reduce across the 4 lanes sharing each pixel row (ties -> smallest index)
    #pragma unroll
    for (int off = 1; off <= 2; off <<= 1) {
        float so0 = __shfl_xor_sync(0xffffffffu, best_s0, off);
        int   io0 = __shfl_xor_sync(0xffffffffu, best_i0, off);
        float so1 = __shfl_xor_sync(0xffffffffu, best_s1, off);
        int   io1 = __shfl_xor_sync(0xffffffffu, best_i1, off);
        if (so0 > best_s0 || (so0 == best_s0 && io0 < best_i0)) { best_s0 = so0; best_i0 = io0; }
        if (so1 > best_s1 || (so1 == best_s1 && io1 < best_i1)) { best_s1 = so1; best_i1 = io1; }
    }
    // combine the two n-halves via packed atomicMax (ties -> smallest index)
    if (r == 0) {
        unsigned u0 = __float_as_uint(best_s0);
        u0 = (u0 & 0x80000000u) ? ~u0 : (u0 | 0x80000000u);
        unsigned u1 = __float_as_uint(best_s1);
        u1 = (u1 & 0x80000000u) ? ~u1 : (u1 | 0x80000000u);
        atomicMax(&sbest[m0 + q],
                  ((unsigned long long)u0 << 32) | (unsigned)(K - 1 - best_i0));
        atomicMax(&sbest[m0 + q + 8],
                  ((unsigned long long)u1 << 32) | (unsigned)(K - 1 - best_i1));
    }
    __syncthreads();

    // outputs: gathered codebook rows (NHWC) + indices (float)
    #pragma unroll
    for (int t = 0; t < 4; t++) {
        int i = tid + t * T;                      // MT*16 = 2048 float4 writes
        int j = i >> 4, c4 = i & 15;
        int idx = (K - 1) - (int)(sbest[j] & 0xffffffffull);
        float4 v = *(const float4*)(embed + idx * D + (c4 << 2));
        *(float4*)(outq + ((size_t)(n0 + j)) * D + (c4 << 2)) = v;
    }
    if (outi && tid < MT)
        outi[n0 + tid] = (float)((K - 1) - (int)(sbest[tid] & 0xffffffffull));
}

// ---------------------------------------------------------------------------
extern "C" void kernel_launch(void* const* d_in, const int* in_sizes, int n_in,
                              void* d_out, int out_size) {
    const float* x = (const float*)d_in[0];
    const float* embed = (const float*)d_in[1];
    float* out = (float*)d_out;

    const int N = in_sizes[0] / D;
    float* outi = nullptr;
    if (out_size >= N * D + N) outi = out + (size_t)N * D;

    cudaFuncSetAttribute(vq_main, cudaFuncAttributeMaxDynamicSharedMemorySize, SMEM_SZ);
    vq_prep<<<K, D>>>(embed);
    vq_main<<<N / MT, T, SMEM_SZ>>>(x, embed, out, outi);
}

// round 7
// speedup vs baseline: 3.2092x; 2.2977x over previous
#include <cuda_runtime.h>
#include <cuda_fp16.h>
#include <cstdint>

// VQ via mma.sync m16n8k16 fp16 (2-split, 3 passes aa+ab+ba ~ exact fp32).
// R7: halve HMMA instruction count vs tf32-k8 (tf32 runs at half rate).
// Whole split codebook resident in SMEM; no mainloop syncs.

#define D    64
#define K    512
#define MT   128     // pixels per CTA
#define T    512     // threads per CTA (16 warps)

// SMEM layout (bytes)
#define SX_OFF    0                       // x tile fp32 [d][m] = [64][128]  32KB
#define BA_OFF    32768                   // codebook a-part [512][128B]     64KB
#define BB_OFF    98304                   // codebook b-part [512][128B]     64KB
#define SHES_OFF  163840                  // 512 f32
#define SBEST_OFF 165888                  // 128 u64
#define SMEM_SZ   166912

__device__ __half g_ea[K * D];   // fp16 hi split, permuted+swizzled rows
__device__ __half g_eb[K * D];   // fp16 lo split, same layout
__device__ float  g_hes[K];      // 0.5*||e||^2

// ---------------- helpers ----------------
__device__ __forceinline__ uint32_t smem_u32(const void* p) {
    uint32_t a;
    asm("{ .reg .u64 t; cvta.to.shared.u64 t, %1; cvt.u32.u64 %0, t; }" : "=r"(a) : "l"(p));
    return a;
}
__device__ __forceinline__ uint32_t pack2(__half x, __half y) {
    __half2 h = __halves2half2(x, y);
    return *(uint32_t*)&h;
}
#define MMA_F16(c, a0, a1, a2, a3, b0, b1)                                       \
    asm volatile("mma.sync.aligned.m16n8k16.row.col.f32.f16.f16.f32 "            \
        "{%0,%1,%2,%3},{%4,%5,%6,%7},{%8,%9},{%0,%1,%2,%3};"                     \
        : "+f"((c)[0]), "+f"((c)[1]), "+f"((c)[2]), "+f"((c)[3])                  \
        : "r"(a0), "r"(a1), "r"(a2), "r"(a3), "r"(b0), "r"(b1))

__device__ __forceinline__ void cp16(uint32_t dst, const void* src) {
    asm volatile("cp.async.cg.shared.global [%0], [%1], 16;" :: "r"(dst), "l"(src) : "memory");
}
#define CP_COMMIT() asm volatile("cp.async.commit_group;" ::: "memory")
#define CP_WAIT(n)  asm volatile("cp.async.wait_group %0;" :: "n"(n) : "memory")

// ---------------- prep ----------------
// Row layout (per code k, 64 fp16 = 128B): element d = 32g+16c+8h+2rr+par goes to
// slot = (4g + rr + 4*(k&1)) & 7 (16B slots), within-slot half idx = (2c+h)*2+par.
// Reader thread (q,r) then gets chunk-frags via one uint4 per 32-k group, and the
// k&1 parity swizzle makes every 8-lane LDS.128 phase hit 8 distinct slots.
__global__ void vq_prep(const float* __restrict__ embed) {
    int k = blockIdx.x, d = threadIdx.x;
    float v = embed[k * D + d];
    __half a = __float2half_rn(v);
    __half bp = __float2half_rn(v - __half2float(a));
    int g = d >> 5, kk = d & 31;
    int rr = (kk >> 1) & 3, h = (kk >> 3) & 1, c = (kk >> 4) & 1, par = kk & 1;
    int slot = ((g << 2) + rr + ((k & 1) << 2)) & 7;
    int pos = k * 64 + slot * 8 + ((c << 1) + h) * 2 + par;
    g_ea[pos] = a;
    g_eb[pos] = bp;
    float s = v * v;
    #pragma unroll
    for (int o = 16; o > 0; o >>= 1) s += __shfl_down_sync(0xffffffffu, s, o);
    __shared__ float ws[2];
    if ((d & 31) == 0) ws[d >> 5] = s;
    __syncthreads();
    if (d == 0) g_hes[k] = 0.5f * (ws[0] + ws[1]);
}

// ---------------- main ----------------
__global__ void __launch_bounds__(T, 1) vq_main(const float* __restrict__ x,
                                                const float* __restrict__ embed,
                                                float* __restrict__ outq,
                                                float* __restrict__ outi) {
    extern __shared__ __align__(1024) char smem[];
    uint32_t sb = smem_u32(smem);
    const int tid = threadIdx.x, wid = tid >> 5, lane = tid & 31;
    const int q = lane >> 2, r = lane & 3;
    const int wm = wid & 7;                  // m-group (16 pixels)
    const int wg = wid >> 3;                 // n-half (tiles 0..31 / 32..63)
    const int n0 = blockIdx.x * MT;
    const int b = n0 >> 12, hw0 = n0 & 4095;

    float* sx = (float*)(smem + SX_OFF);     // [d][128]
    float* shes = (float*)(smem + SHES_OFF);
    unsigned long long* sbest = (unsigned long long*)(smem + SBEST_OFF);

    // stage whole split codebook (128KB, L2-resident) via cp.async
    #pragma unroll
    for (int t = 0; t < 8; t++) {
        int c = tid + t * T;                 // 4096 16B chunks per part
        cp16(sb + BA_OFF + c * 16, (const char*)g_ea + c * 16);
        cp16(sb + BB_OFF + c * 16, (const char*)g_eb + c * 16);
    }
    CP_COMMIT();

    // stage x tile: sx[c][j] = x[b][c][hw0+j]
    #pragma unroll
    for (int t = 0; t < 4; t++) {
        int i = tid + t * T;
        int c = i >> 5, j4 = (i & 31) << 2;
        float4 v = *(const float4*)(x + (((size_t)(b * D + c)) << 12) + hw0 + j4);
        *(float4*)(sx + c * MT + j4) = v;
    }
    if (tid < K) shes[tid] = g_hes[tid];
    if (tid < MT) sbest[tid] = 0ull;
    CP_WAIT(0);
    __syncthreads();

    // A fragments (fp16 2-split) in registers: rows m0+q, m0+q+8.
    // Aa[cc][reg]: reg = {rowq k-lo, rowq+8 k-lo, rowq k-hi, rowq+8 k-hi}, k-lo=16cc+2r.
    const int m0 = wm * 16;
    uint32_t Aa[4][4], Ab[4][4];
    #pragma unroll
    for (int cc = 0; cc < 4; cc++) {
        #pragma unroll
        for (int hh = 0; hh < 2; hh++) {
            int k = 16 * cc + 2 * r + 8 * hh;
            float f0a = sx[k * MT + m0 + q],     f1a = sx[(k + 1) * MT + m0 + q];
            float f0b = sx[k * MT + m0 + q + 8], f1b = sx[(k + 1) * MT + m0 + q + 8];
            __half a0 = __float2half_rn(f0a), a1 = __float2half_rn(f1a);
            __half b0 = __float2half_rn(f0b), b1 = __float2half_rn(f1b);
            Aa[cc][2 * hh]     = pack2(a0, a1);
            Aa[cc][2 * hh + 1] = pack2(b0, b1);
            Ab[cc][2 * hh]     = pack2(__float2half_rn(f0a - __half2float(a0)),
                                       __float2half_rn(f1a - __half2float(a1)));
            Ab[cc][2 * hh + 1] = pack2(__float2half_rn(f0b - __half2float(b0)),
                                       __float2half_rn(f1b - __half2float(b1)));
        }
    }

    float best_s0 = -3.0e38f, best_s1 = -3.0e38f;
    int best_i0 = 0, best_i1 = 0;

    #pragma unroll 1
    for (int tg = 0; tg < 8; tg++) {
        const int t0 = wg * 32 + tg * 4;         // 4 n-tiles (8 codes each) in flight
        float acc[4][4];
        #pragma unroll
        for (int j = 0; j < 4; j++)
            #pragma unroll
            for (int c = 0; c < 4; c++) acc[j][c] = 0.0f;

        #pragma unroll
        for (int p = 0; p < 3; p++) {            // passes: Aa*Ba, Aa*Bb, Ab*Ba
            const uint32_t (*pa)[4] = (p == 2) ? Ab : Aa;
            const char* bbase = smem + ((p == 1) ? BB_OFF : BA_OFF);
            #pragma unroll
            for (int j = 0; j < 4; j++) {
                int n = (t0 + j) * 8 + q;
                const char* row = bbase + n * 128;
                int so = r + ((n & 1) << 2);
                uint4 v0 = *(const uint4*)(row + (so & 7) * 16);          // k 0..31
                uint4 v1 = *(const uint4*)(row + ((so + 4) & 7) * 16);    // k 32..63
                MMA_F16(acc[j], pa[0][0], pa[0][1], pa[0][2], pa[0][3], v0.x, v0.y);
                MMA_F16(acc[j], pa[1][0], pa[1][1], pa[1][2], pa[1][3], v0.z, v0.w);
                MMA_F16(acc[j], pa[2][0], pa[2][1], pa[2][2], pa[2][3], v1.x, v1.y);
                MMA_F16(acc[j], pa[3][0], pa[3][1], pa[3][2], pa[3][3], v1.z, v1.w);
            }
        }
        #pragma unroll
        for (int j = 0; j < 4; j++) {
            int cb = (t0 + j) * 8 + 2 * r;
            float h0 = shes[cb], h1 = shes[cb + 1];
            float s00 = acc[j][0] - h0, s01 = acc[j][1] - h1;
            float s10 = acc[j][2] - h0, s11 = acc[j][3] - h1;
            if (s00 > best_s0) { best_s0 = s00; best_i0 = cb; }
            if (s01 > best_s0) { best_s0 = s01; best_i0 = cb + 1; }
            if (s10 > best_s1) { best_s1 = s10; best_i1 = cb; }
            if (s11 > best_s1) { best_s1 = s11; best_i1 = cb + 1; }
        }
    }

    // reduce across the 4 lanes sharing each pixel row (ties -> smallest index)
    #pragma unroll
    for (int off = 1; off <= 2; off <<= 1) {
        float so0 = __shfl_xor_sync(0xffffffffu, best_s0, off);
        int   io0 = __shfl_xor_sync(0xffffffffu, best_i0, off);
        float so1 = __shfl_xor_sync(0xffffffffu, best_s1, off);
        int   io1 = __shfl_xor_sync(0xffffffffu, best_i1, off);
        if (so0 > best_s0 || (so0 == best_s0 && io0 < best_i0)) { best_s0 = so0; best_i0 = io0; }
        if (so1 > best_s1 || (so1 == best_s1 && io1 < best_i1)) { best_s1 = so1; best_i1 = io1; }
    }
    // combine the two n-halves via packed atomicMax (ties -> smallest index)
    if (r == 0) {
        unsigned u0 = __float_as_uint(best_s0);
        u0 = (u0 & 0x80000000u) ? ~u0 : (u0 | 0x80000000u);
        unsigned u1 = __float_as_uint(best_s1);
        u1 = (u1 & 0x80000000u) ? ~u1 : (u1 | 0x80000000u);
        atomicMax(&sbest[m0 + q],
                  ((unsigned long long)u0 << 32) | (unsigned)(K - 1 - best_i0));
        atomicMax(&sbest[m0 + q + 8],
                  ((unsigned long long)u1 << 32) | (unsigned)(K - 1 - best_i1));
    }
    __syncthreads();

    // outputs: gathered codebook rows (NHWC) + indices (float)
    #pragma unroll
    for (int t = 0; t < 4; t++) {
        int i = tid + t * T;                      // MT*16 = 2048 float4 writes
        int j = i >> 4, c4 = i & 15;
        int idx = (K - 1) - (int)(sbest[j] & 0xffffffffull);
        float4 v = *(const float4*)(embed + idx * D + (c4 << 2));
        *(float4*)(outq + ((size_t)(n0 + j)) * D + (c4 << 2)) = v;
    }
    if (outi && tid < MT)
        outi[n0 + tid] = (float)((K - 1) - (int)(sbest[tid] & 0xffffffffull));
}

// ---------------------------------------------------------------------------
extern "C" void kernel_launch(void* const* d_in, const int* in_sizes, int n_in,
                              void* d_out, int out_size) {
    const float* x = (const float*)d_in[0];
    const float* embed = (const float*)d_in[1];
    float* out = (float*)d_out;

    const int N = in_sizes[0] / D;
    float* outi = nullptr;
    if (out_size >= N * D + N) outi = out + (size_t)N * D;

    cudaFuncSetAttribute(vq_main, cudaFuncAttributeMaxDynamicSharedMemorySize, SMEM_SZ);
    vq_prep<<<K, D>>>(embed);
    vq_main<<<N / MT, T, SMEM_SZ>>>(x, embed, out, outi);
}

// round 8
// speedup vs baseline: 3.2725x; 1.0197x over previous
#include <cuda_runtime.h>
#include <cuda_fp16.h>
#include <cstdint>

// VQ via mma.sync m16n8k16 fp16 (2-split, 3 passes aa+ab+ba ~ exact fp32).
// R8: reuse Ba fragment for both Aa and Ab passes (LDS.128 per tile 6 -> 4);
// crossbar drops below tensor-pipe time, tensor becomes the binding pipe.

#define D    64
#define K    512
#define MT   128     // pixels per CTA
#define T    512     // threads per CTA (16 warps)

// SMEM layout (bytes)
#define SX_OFF    0                       // x tile fp32 [d][m] = [64][128]  32KB
#define BA_OFF    32768                   // codebook a-part [512][128B]     64KB
#define BB_OFF    98304                   // codebook b-part [512][128B]     64KB
#define SHES_OFF  163840                  // 512 f32
#define SBEST_OFF 165888                  // 128 u64
#define SMEM_SZ   166912

__device__ __half g_ea[K * D];   // fp16 hi split, permuted+swizzled rows
__device__ __half g_eb[K * D];   // fp16 lo split, same layout
__device__ float  g_hes[K];      // 0.5*||e||^2

// ---------------- helpers ----------------
__device__ __forceinline__ uint32_t smem_u32(const void* p) {
    uint32_t a;
    asm("{ .reg .u64 t; cvta.to.shared.u64 t, %1; cvt.u32.u64 %0, t; }" : "=r"(a) : "l"(p));
    return a;
}
__device__ __forceinline__ uint32_t pack2(__half x, __half y) {
    __half2 h = __halves2half2(x, y);
    return *(uint32_t*)&h;
}
#define MMA_F16(c, a0, a1, a2, a3, b0, b1)                                       \
    asm volatile("mma.sync.aligned.m16n8k16.row.col.f32.f16.f16.f32 "            \
        "{%0,%1,%2,%3},{%4,%5,%6,%7},{%8,%9},{%0,%1,%2,%3};"                     \
        : "+f"((c)[0]), "+f"((c)[1]), "+f"((c)[2]), "+f"((c)[3])                  \
        : "r"(a0), "r"(a1), "r"(a2), "r"(a3), "r"(b0), "r"(b1))

__device__ __forceinline__ void cp16(uint32_t dst, const void* src) {
    asm volatile("cp.async.cg.shared.global [%0], [%1], 16;" :: "r"(dst), "l"(src) : "memory");
}
#define CP_COMMIT() asm volatile("cp.async.commit_group;" ::: "memory")
#define CP_WAIT(n)  asm volatile("cp.async.wait_group %0;" :: "n"(n) : "memory")

// ---------------- prep ----------------
// Row layout (per code k, 64 fp16 = 128B): element d = 32g+16c+8h+2rr+par goes to
// slot = (4g + rr + 4*(k&1)) & 7 (16B slots), within-slot half idx = (2c+h)*2+par.
// k&1 parity swizzle makes every 8-lane LDS.128 phase hit 8 distinct slots.
__global__ void vq_prep(const float* __restrict__ embed) {
    int k = blockIdx.x, d = threadIdx.x;
    float v = embed[k * D + d];
    __half a = __float2half_rn(v);
    __half bp = __float2half_rn(v - __half2float(a));
    int g = d >> 5, kk = d & 31;
    int rr = (kk >> 1) & 3, h = (kk >> 3) & 1, c = (kk >> 4) & 1, par = kk & 1;
    int slot = ((g << 2) + rr + ((k & 1) << 2)) & 7;
    int pos = k * 64 + slot * 8 + ((c << 1) + h) * 2 + par;
    g_ea[pos] = a;
    g_eb[pos] = bp;
    float s = v * v;
    #pragma unroll
    for (int o = 16; o > 0; o >>= 1) s += __shfl_down_sync(0xffffffffu, s, o);
    __shared__ float ws[2];
    if ((d & 31) == 0) ws[d >> 5] = s;
    __syncthreads();
    if (d == 0) g_hes[k] = 0.5f * (ws[0] + ws[1]);
}

// ---------------- main ----------------
__global__ void __launch_bounds__(T, 1) vq_main(const float* __restrict__ x,
                                                const float* __restrict__ embed,
                                                float* __restrict__ outq,
                                                float* __restrict__ outi) {
    extern __shared__ __align__(1024) char smem[];
    uint32_t sb = smem_u32(smem);
    const int tid = threadIdx.x, wid = tid >> 5, lane = tid & 31;
    const int q = lane >> 2, r = lane & 3;
    const int wm = wid & 7;                  // m-group (16 pixels)
    const int wg = wid >> 3;                 // n-half (tiles 0..31 / 32..63)
    const int n0 = blockIdx.x * MT;
    const int b = n0 >> 12, hw0 = n0 & 4095;

    float* sx = (float*)(smem + SX_OFF);     // [d][128]
    float* shes = (float*)(smem + SHES_OFF);
    unsigned long long* sbest = (unsigned long long*)(smem + SBEST_OFF);

    // stage whole split codebook (128KB, L2-resident) via cp.async
    #pragma unroll
    for (int t = 0; t < 8; t++) {
        int c = tid + t * T;                 // 4096 16B chunks per part
        cp16(sb + BA_OFF + c * 16, (const char*)g_ea + c * 16);
        cp16(sb + BB_OFF + c * 16, (const char*)g_eb + c * 16);
    }
    CP_COMMIT();

    // stage x tile: sx[c][j] = x[b][c][hw0+j]
    #pragma unroll
    for (int t = 0; t < 4; t++) {
        int i = tid + t * T;
        int c = i >> 5, j4 = (i & 31) << 2;
        float4 v = *(const float4*)(x + (((size_t)(b * D + c)) << 12) + hw0 + j4);
        *(float4*)(sx + c * MT + j4) = v;
    }
    if (tid < K) shes[tid] = g_hes[tid];
    if (tid < MT) sbest[tid] = 0ull;
    CP_WAIT(0);
    __syncthreads();

    // A fragments (fp16 2-split) in registers: rows m0+q, m0+q+8.
    // Aa[cc][reg]: reg = {rowq k-lo, rowq+8 k-lo, rowq k-hi, rowq+8 k-hi}, k-lo=16cc+2r.
    const int m0 = wm * 16;
    uint32_t Aa[4][4], Ab[4][4];
    #pragma unroll
    for (int cc = 0; cc < 4; cc++) {
        #pragma unroll
        for (int hh = 0; hh < 2; hh++) {
            int k = 16 * cc + 2 * r + 8 * hh;
            float f0a = sx[k * MT + m0 + q],     f1a = sx[(k + 1) * MT + m0 + q];
            float f0b = sx[k * MT + m0 + q + 8], f1b = sx[(k + 1) * MT + m0 + q + 8];
            __half a0 = __float2half_rn(f0a), a1 = __float2half_rn(f1a);
            __half b0 = __float2half_rn(f0b), b1 = __float2half_rn(f1b);
            Aa[cc][2 * hh]     = pack2(a0, a1);
            Aa[cc][2 * hh + 1] = pack2(b0, b1);
            Ab[cc][2 * hh]     = pack2(__float2half_rn(f0a - __half2float(a0)),
                                       __float2half_rn(f1a - __half2float(a1)));
            Ab[cc][2 * hh + 1] = pack2(__float2half_rn(f0b - __half2float(b0)),
                                       __float2half_rn(f1b - __half2float(b1)));
        }
    }

    float best_s0 = -3.0e38f, best_s1 = -3.0e38f;
    int best_i0 = 0, best_i1 = 0;

    #pragma unroll 1
    for (int tg = 0; tg < 8; tg++) {
        const int t0 = wg * 32 + tg * 4;         // 4 n-tiles (8 codes each) in flight
        float acc[4][4];
        #pragma unroll
        for (int j = 0; j < 4; j++)
            #pragma unroll
            for (int c = 0; c < 4; c++) acc[j][c] = 0.0f;

        // per tile: Ba once (feeds Aa and Ab passes), then Bb (feeds Aa)
        #pragma unroll
        for (int j = 0; j < 4; j++) {
            int n = (t0 + j) * 8 + q;
            const char* rowa = smem + BA_OFF + n * 128;
            const char* rowb = smem + BB_OFF + n * 128;
            int so = r + ((n & 1) << 2);
            int s0 = (so & 7) * 16, s1 = ((so + 4) & 7) * 16;

            uint4 va0 = *(const uint4*)(rowa + s0);          // k 0..31 of Ba
            uint4 va1 = *(const uint4*)(rowa + s1);          // k 32..63 of Ba
            MMA_F16(acc[j], Aa[0][0], Aa[0][1], Aa[0][2], Aa[0][3], va0.x, va0.y);
            MMA_F16(acc[j], Aa[1][0], Aa[1][1], Aa[1][2], Aa[1][3], va0.z, va0.w);
            MMA_F16(acc[j], Aa[2][0], Aa[2][1], Aa[2][2], Aa[2][3], va1.x, va1.y);
            MMA_F16(acc[j], Aa[3][0], Aa[3][1], Aa[3][2], Aa[3][3], va1.z, va1.w);
            MMA_F16(acc[j], Ab[0][0], Ab[0][1], Ab[0][2], Ab[0][3], va0.x, va0.y);
            MMA_F16(acc[j], Ab[1][0], Ab[1][1], Ab[1][2], Ab[1][3], va0.z, va0.w);
            MMA_F16(acc[j], Ab[2][0], Ab[2][1], Ab[2][2], Ab[2][3], va1.x, va1.y);
            MMA_F16(acc[j], Ab[3][0], Ab[3][1], Ab[3][2], Ab[3][3], va1.z, va1.w);

            uint4 vb0 = *(const uint4*)(rowb + s0);          // k 0..31 of Bb
            uint4 vb1 = *(const uint4*)(rowb + s1);          // k 32..63 of Bb
            MMA_F16(acc[j], Aa[0][0], Aa[0][1], Aa[0][2], Aa[0][3], vb0.x, vb0.y);
            MMA_F16(acc[j], Aa[1][0], Aa[1][1], Aa[1][2], Aa[1][3], vb0.z, vb0.w);
            MMA_F16(acc[j], Aa[2][0], Aa[2][1], Aa[2][2], Aa[2][3], vb1.x, vb1.y);
            MMA_F16(acc[j], Aa[3][0], Aa[3][1], Aa[3][2], Aa[3][3], vb1.z, vb1.w);
        }

        #pragma unroll
        for (int j = 0; j < 4; j++) {
            int cb = (t0 + j) * 8 + 2 * r;
            float h0 = shes[cb], h1 = shes[cb + 1];
            float s00 = acc[j][0] - h0, s01 = acc[j][1] - h1;
            float s10 = acc[j][2] - h0, s11 = acc[j][3] - h1;
            if (s00 > best_s0) { best_s0 = s00; best_i0 = cb; }
            if (s01 > best_s0) { best_s0 = s01; best_i0 = cb + 1; }
            if (s10 > best_s1) { best_s1 = s10; best_i1 = cb; }
            if (s11 > best_s1) { best_s1 = s11; best_i1 = cb + 1; }
        }
    }

    // reduce across the 4 lanes sharing each pixel row (ties -> smallest index)
    #pragma unroll
    for (int off = 1; off <= 2; off <<= 1) {
        float so0 = __shfl_xor_sync(0xffffffffu, best_s0, off);
        int   io0 = __shfl_xor_sync(0xffffffffu, best_i0, off);
        float so1 = __shfl_xor_sync(0xffffffffu, best_s1, off);
        int   io1 = __shfl_xor_sync(0xffffffffu, best_i1, off);
        if (so0 > best_s0 || (so0 == best_s0 && io0 < best_i0)) { best_s0 = so0; best_i0 = io0; }
        if (so1 > best_s1 || (so1 == best_s1 && io1 < best_i1)) { best_s1 = so1; best_i1 = io1; }
    }
    // combine the two n-halves via packed atomicMax (ties -> smallest index)
    if (r == 0) {
        unsigned u0 = __float_as_uint(best_s0);
        u0 = (u0 & 0x80000000u) ? ~u0 : (u0 | 0x80000000u);
        unsigned u1 = __float_as_uint(best_s1);
        u1 = (u1 & 0x80000000u) ? ~u1 : (u1 | 0x80000000u);
        atomicMax(&sbest[m0 + q],
                  ((unsigned long long)u0 << 32) | (unsigned)(K - 1 - best_i0));
        atomicMax(&sbest[m0 + q + 8],
                  ((unsigned long long)u1 << 32) | (unsigned)(K - 1 - best_i1));
    }
    __syncthreads();

    // outputs: gathered codebook rows (NHWC) + indices (float)
    #pragma unroll
    for (int t = 0; t < 4; t++) {
        int i = tid + t * T;                      // MT*16 = 2048 float4 writes
        int j = i >> 4, c4 = i & 15;
        int idx = (K - 1) - (int)(sbest[j] & 0xffffffffull);
        float4 v = *(const float4*)(embed + idx * D + (c4 << 2));
        *(float4*)(outq + ((size_t)(n0 + j)) * D + (c4 << 2)) = v;
    }
    if (outi && tid < MT)
        outi[n0 + tid] = (float)((K - 1) - (int)(sbest[tid] & 0xffffffffull));
}

// ---------------------------------------------------------------------------
extern "C" void kernel_launch(void* const* d_in, const int* in_sizes, int n_in,
                              void* d_out, int out_size) {
    const float* x = (const float*)d_in[0];
    const float* embed = (const float*)d_in[1];
    float* out = (float*)d_out;

    const int N = in_sizes[0] / D;
    float* outi = nullptr;
    if (out_size >= N * D + N) outi = out + (size_t)N * D;

    cudaFuncSetAttribute(vq_main, cudaFuncAttributeMaxDynamicSharedMemorySize, SMEM_SZ);
    vq_prep<<<K, D>>>(embed);
    vq_main<<<N / MT, T, SMEM_SZ>>>(x, embed, out, outi);
}